// round 5
// baseline (speedup 1.0000x reference)
#include <cuda_runtime.h>
#include <cuda_bf16.h>

#define TPB 256  // 8 warps per block

// Single fused kernel. Each warp owns TWO rows (r, r + total_warps) with
// explicit 4-deep x 2-row load batches (8 LDG.128 in flight). Each block
// independently verifies the Cayley table is cyclic Z_n (L2-resident, ~free),
// choosing fast sum-mod path vs general group-product fallback.
__global__ void __launch_bounds__(TPB) a5_scan_kernel(
    const float* __restrict__ scale_p,
    const int* __restrict__ ids,
    const int* __restrict__ mul,
    float* __restrict__ out,
    int n, int b_rows, int t_len, int total_warps)
{
    __shared__ int s_ok;
    int tid  = threadIdx.x;
    int lane = tid & 31;
    int warp0 = (int)((blockIdx.x * (unsigned)TPB + tid) >> 5);

    // ---- Per-block cyclic check (overlapped across blocks, L2-resident) ----
    if (tid == 0) s_ok = 1;
    __syncthreads();
    {
        int total = n * n;
        for (int i = tid; i < total; i += TPB) {
            int a = i / n;
            int b = i - a * n;
            int e = a + b;
            if (e >= n) e -= n;
            if (__ldg(mul + i) != e) s_ok = 0;   // benign race: all write 0
        }
    }
    __syncthreads();
    bool cyclic = (s_ok != 0);

    float sc = __ldg(scale_p);
    float hi = 10.0f * sc;
    float lo = -10.0f * sc;

    int nvec = t_len >> 2;
    bool vec_ok = ((t_len & 3) == 0);

    for (int r = warp0; r < b_rows; r += 2 * total_warps) {
        int r2 = r + total_warps;
        bool have2 = (r2 < b_rows);

        if (cyclic && vec_ok) {
            const int4* p0 = (const int4*)(ids + (long long)r * t_len);
            const int4* p1 = (const int4*)(ids + (long long)(have2 ? r2 : r) * t_len);
            int s0 = 0, s1 = 0;
            int j = lane;

            // Full 4-deep batches: 8 independent LDG.128 per iteration.
            for (; j + 3 * 32 < nvec; j += 4 * 32) {
                int4 a[4], b[4];
                #pragma unroll
                for (int u = 0; u < 4; u++) a[u] = __ldg(p0 + j + u * 32);
                #pragma unroll
                for (int u = 0; u < 4; u++) b[u] = __ldg(p1 + j + u * 32);
                #pragma unroll
                for (int u = 0; u < 4; u++) {
                    s0 += a[u].x + a[u].y + a[u].z + a[u].w;
                    s1 += b[u].x + b[u].y + b[u].z + b[u].w;
                }
            }
            // Remainder
            for (; j < nvec; j += 32) {
                int4 a = __ldg(p0 + j);
                int4 b = __ldg(p1 + j);
                s0 += a.x + a.y + a.z + a.w;
                s1 += b.x + b.y + b.z + b.w;
            }

            #pragma unroll
            for (int d = 16; d; d >>= 1) {
                s0 += __shfl_xor_sync(0xffffffffu, s0, d);
                s1 += __shfl_xor_sync(0xffffffffu, s1, d);
            }
            int sa = s0 % n;
            int sb = s1 % n;

            float* o0 = out + (long long)r * n;
            for (int i = lane; i < n; i += 32)
                o0[i] = (i == sa) ? hi : lo;
            if (have2) {
                float* o1 = out + (long long)r2 * n;
                for (int i = lane; i < n; i += 32)
                    o1[i] = (i == sb) ? hi : lo;
            }
        } else {
            // General ordered group product fallback (per row)
            for (int k = 0; k < 2; k++) {
                int rr = (k == 0) ? r : r2;
                if (k == 1 && !have2) break;
                const int* row = ids + (long long)rr * t_len;
                int s;
                if ((t_len & 31) == 0) {
                    int chunk = t_len >> 5;
                    const int* base = row + lane * chunk;
                    int q = 0;                       // identity
                    for (int j = 0; j < chunk; j++) {
                        int x = __ldg(base + j);
                        q = __ldg(mul + x * n + q);  // q = x . q
                    }
                    #pragma unroll
                    for (int d = 1; d < 32; d <<= 1) {
                        int t = __shfl_up_sync(0xffffffffu, q, d);
                        if (lane >= d) q = __ldg(mul + q * n + t);
                    }
                    s = __shfl_sync(0xffffffffu, q, 31);
                } else {
                    int q = 0;
                    if (lane == 0)
                        for (int j = 0; j < t_len; j++)
                            q = __ldg(mul + __ldg(row + j) * n + q);
                    s = __shfl_sync(0xffffffffu, q, 0);
                }
                float* orow = out + (long long)rr * n;
                for (int i = lane; i < n; i += 32)
                    orow[i] = (i == s) ? hi : lo;
            }
        }
    }
}

extern "C" void kernel_launch(void* const* d_in, const int* in_sizes, int n_in,
                              void* d_out, int out_size) {
    const float* scale = (const float*)d_in[0];
    const int*   ids   = (const int*)d_in[1];
    const int*   mul   = (const int*)d_in[2];
    float*       out   = (float*)d_out;

    int mn = in_sizes[2];
    int n = 1;
    while (n * n < mn) n++;

    int b_rows = out_size / n;              // 8192
    int t_len  = in_sizes[1] / b_rows;      // 2048

    // 2 rows per warp -> 16 rows per 8-warp block -> 512 blocks (one wave).
    const int warps_per_block = TPB / 32;
    int blocks = (b_rows + 2 * warps_per_block - 1) / (2 * warps_per_block);
    int total_warps = blocks * warps_per_block;

    a5_scan_kernel<<<blocks, TPB>>>(scale, ids, mul, out,
                                    n, b_rows, t_len, total_warps);
}

// round 6
// speedup vs baseline: 1.1200x; 1.1200x over previous
#include <cuda_runtime.h>
#include <cuda_bf16.h>

__device__ int g_is_cyclic;

// Separate small node (R4-proven cheap): 1 block x 1024 threads.
__global__ void __launch_bounds__(1024) check_cyclic_kernel(
    const int* __restrict__ mul, int n)
{
    __shared__ int ok;
    if (threadIdx.x == 0) ok = 1;
    __syncthreads();
    int total = n * n;
    for (int i = threadIdx.x; i < total; i += 1024) {
        int a = i / n;
        int b = i - a * n;
        int e = a + b;
        if (e >= n) e -= n;
        if (__ldg(mul + i) != e) ok = 0;   // benign race: all writers store 0
    }
    __syncthreads();
    if (threadIdx.x == 0) g_is_cyclic = ok;
}

#define TPB 128  // 4 warps per block -> 1024 blocks -> 6.92 blocks/SM (balanced)

// Each warp owns TWO rows (r, r + total_warps), loads interleaved (R4-proven
// body). Grid shape chosen for near-perfect CTA->SM balance in one wave.
__global__ void __launch_bounds__(TPB) a5_scan_kernel(
    const float* __restrict__ scale_p,
    const int* __restrict__ ids,
    const int* __restrict__ mul,
    float* __restrict__ out,
    int n, int b_rows, int t_len, int total_warps)
{
    int lane  = threadIdx.x & 31;
    int warp0 = (int)((blockIdx.x * (unsigned)TPB + threadIdx.x) >> 5);
    bool cyclic = (g_is_cyclic != 0);

    float sc = __ldg(scale_p);
    float hi = 10.0f * sc;
    float lo = -10.0f * sc;

    int nvec = t_len >> 2;
    bool vec_ok = ((t_len & 3) == 0);

    for (int r = warp0; r < b_rows; r += 2 * total_warps) {
        int r2 = r + total_warps;
        bool have2 = (r2 < b_rows);

        if (cyclic && vec_ok) {
            const int4* p0 = (const int4*)(ids + (long long)r * t_len);
            const int4* p1 = (const int4*)(ids + (long long)(have2 ? r2 : r) * t_len);
            int s0 = 0, s1 = 0;
            #pragma unroll 4
            for (int j = lane; j < nvec; j += 32) {
                int4 a = __ldg(p0 + j);
                int4 b = __ldg(p1 + j);
                s0 += a.x + a.y + a.z + a.w;
                s1 += b.x + b.y + b.z + b.w;
            }
            #pragma unroll
            for (int d = 16; d; d >>= 1) {
                s0 += __shfl_xor_sync(0xffffffffu, s0, d);
                s1 += __shfl_xor_sync(0xffffffffu, s1, d);
            }
            int sa = s0 % n;
            int sb = s1 % n;

            float* o0 = out + (long long)r * n;
            for (int i = lane; i < n; i += 32)
                o0[i] = (i == sa) ? hi : lo;
            if (have2) {
                float* o1 = out + (long long)r2 * n;
                for (int i = lane; i < n; i += 32)
                    o1[i] = (i == sb) ? hi : lo;
            }
        } else {
            // General ordered group product fallback (per row)
            for (int k = 0; k < 2; k++) {
                int rr = (k == 0) ? r : r2;
                if (k == 1 && !have2) break;
                const int* row = ids + (long long)rr * t_len;
                int s;
                if ((t_len & 31) == 0) {
                    int chunk = t_len >> 5;
                    const int* base = row + lane * chunk;
                    int q = 0;                       // identity
                    for (int j = 0; j < chunk; j++) {
                        int x = __ldg(base + j);
                        q = __ldg(mul + x * n + q);  // q = x . q
                    }
                    #pragma unroll
                    for (int d = 1; d < 32; d <<= 1) {
                        int t = __shfl_up_sync(0xffffffffu, q, d);
                        if (lane >= d) q = __ldg(mul + q * n + t);
                    }
                    s = __shfl_sync(0xffffffffu, q, 31);
                } else {
                    int q = 0;
                    if (lane == 0)
                        for (int j = 0; j < t_len; j++)
                            q = __ldg(mul + __ldg(row + j) * n + q);
                    s = __shfl_sync(0xffffffffu, q, 0);
                }
                float* orow = out + (long long)rr * n;
                for (int i = lane; i < n; i += 32)
                    orow[i] = (i == s) ? hi : lo;
            }
        }
    }
}

extern "C" void kernel_launch(void* const* d_in, const int* in_sizes, int n_in,
                              void* d_out, int out_size) {
    const float* scale = (const float*)d_in[0];
    const int*   ids   = (const int*)d_in[1];
    const int*   mul   = (const int*)d_in[2];
    float*       out   = (float*)d_out;

    int mn = in_sizes[2];
    int n = 1;
    while (n * n < mn) n++;

    int b_rows = out_size / n;              // 8192
    int t_len  = in_sizes[1] / b_rows;      // 2048

    check_cyclic_kernel<<<1, 1024>>>(mul, n);

    // 2 rows per warp -> 8 rows per 4-warp block -> 1024 blocks (one wave,
    // 6.92 blocks/SM: near-perfect SM balance vs 512-block 3.46/SM shape).
    const int warps_per_block = TPB / 32;
    int blocks = (b_rows + 2 * warps_per_block - 1) / (2 * warps_per_block);
    int total_warps = blocks * warps_per_block;

    a5_scan_kernel<<<blocks, TPB>>>(scale, ids, mul, out,
                                    n, b_rows, t_len, total_warps);
}